// round 3
// baseline (speedup 1.0000x reference)
#include <cuda_runtime.h>

#define BB 512
#define TT 4096
#define IDIM 8
#define HH 64
#define GG 256
#define XCHUNK 128
#define NTHREADS 256

typedef unsigned long long ull;

// packed f32x2 FMA: d = a*b + c elementwise on two packed floats
static __device__ __forceinline__ ull dfma2(ull a, ull b, ull c) {
    ull d;
    asm("fma.rn.f32x2 %0, %1, %2, %3;" : "=l"(d) : "l"(a), "l"(b), "l"(c));
    return d;
}
static __device__ __forceinline__ float lo2(ull v) {
    return __int_as_float((int)(unsigned)(v & 0xffffffffull));
}
static __device__ __forceinline__ float hi2(ull v) {
    return __int_as_float((int)(unsigned)(v >> 32));
}

static __device__ __forceinline__ float sigf(float x) {
    return 1.0f / (1.0f + __expf(-x));
}
static __device__ __forceinline__ float tanh_f(float x) {
    float xc = fminf(fmaxf(x, -15.0f), 15.0f);
    float e = __expf(2.0f * xc);
    return 1.0f - 2.0f / (e + 1.0f);
}

static __device__ __forceinline__ void cp_async16(void* smem, const void* gmem) {
    unsigned saddr = (unsigned)__cvta_generic_to_shared(smem);
    asm volatile("cp.async.cg.shared.global [%0], [%1], 16;\n" :: "r"(saddr), "l"(gmem));
}

__global__ void __launch_bounds__(NTHREADS, 1)
lstm2_kernel(const float* __restrict__ x,
             const float* __restrict__ Wih0, const float* __restrict__ Whh0,
             const float* __restrict__ bih0, const float* __restrict__ bhh0,
             const float* __restrict__ Wih1, const float* __restrict__ Whh1,
             const float* __restrict__ bih1, const float* __restrict__ bhh1,
             const float* __restrict__ fcw, const float* __restrict__ fcb,
             float* __restrict__ out)
{
    const int b = blockIdx.x;
    const int g = threadIdx.x;

    __shared__ __align__(16) float xbuf[2][XCHUNK * IDIM];  // 2 x 4KB
    __shared__ __align__(16) float h0s[HH];
    __shared__ __align__(16) float h1s[HH];
    __shared__ __align__(16) float g0s[GG];
    __shared__ __align__(16) float g1s[GG];

    // ---- load this thread's gate-row weights into registers (packed f32x2) ----
    ull wih0[IDIM / 2], whh0[HH / 2], wih1[HH / 2], whh1[HH / 2];
    {
        const ull* p = (const ull*)(Wih0 + g * IDIM);
#pragma unroll
        for (int i = 0; i < IDIM / 2; i++) wih0[i] = p[i];
        p = (const ull*)(Whh0 + g * HH);
#pragma unroll
        for (int i = 0; i < HH / 2; i++) whh0[i] = p[i];
        p = (const ull*)(Wih1 + g * HH);
#pragma unroll
        for (int i = 0; i < HH / 2; i++) wih1[i] = p[i];
        p = (const ull*)(Whh1 + g * HH);
#pragma unroll
        for (int i = 0; i < HH / 2; i++) whh1[i] = p[i];
    }
    const float bias0 = bih0[g] + bhh0[g];
    const float bias1 = bih1[g] + bhh1[g];

    // ---- init state ----
    if (g < HH) h0s[g] = 0.0f;
    else if (g < 2 * HH) h1s[g - HH] = 0.0f;
    float c0 = 0.0f;  // owned by threads [0,64)
    float c1 = 0.0f;  // owned by threads [64,128)

    const float* xb = x + (size_t)b * TT * IDIM;

    // prefetch x chunk 0
    cp_async16(&xbuf[0][g * 4], xb + g * 4);
    asm volatile("cp.async.commit_group;\n" ::: "memory");

    const int nchunks = TT / XCHUNK;

    // Iteration t: layer0 step t  +  layer1 step (t-1)   [pipeline skew]
    for (int t = 0; t < TT; ++t) {
        const int tc = t & (XCHUNK - 1);
        const int cur = (t / XCHUNK) & 1;
        if (tc == 0) {
            asm volatile("cp.async.wait_group 0;\n" ::: "memory");
            __syncthreads();
            const int nxt = t / XCHUNK + 1;
            if (nxt < nchunks) {
                cp_async16(&xbuf[cur ^ 1][g * 4], xb + (size_t)nxt * XCHUNK * IDIM + g * 4);
                asm volatile("cp.async.commit_group;\n" ::: "memory");
            }
        }

        // ---------- phase A: all 256 threads compute gate dot products ----------
        ull a0 = 0, a1 = 0;              // layer0 accumulators
        ull q0 = 0, q1 = 0, q2 = 0, q3 = 0;  // layer1 accumulators
        {
            const longlong2* h0d = (const longlong2*)h0s;
#pragma unroll
            for (int i = 0; i < HH / 4; i++) {
                longlong2 hd = h0d[i];
                ull hlo = (ull)hd.x, hhi = (ull)hd.y;
                a0 = dfma2(whh0[2 * i],     hlo, a0);
                a1 = dfma2(whh0[2 * i + 1], hhi, a1);
                q0 = dfma2(wih1[2 * i],     hlo, q0);
                q1 = dfma2(wih1[2 * i + 1], hhi, q1);
            }
            const longlong2* h1d = (const longlong2*)h1s;
#pragma unroll
            for (int i = 0; i < HH / 4; i++) {
                longlong2 hd = h1d[i];
                q2 = dfma2(whh1[2 * i],     (ull)hd.x, q2);
                q3 = dfma2(whh1[2 * i + 1], (ull)hd.y, q3);
            }
            const longlong2* xd = (const longlong2*)&xbuf[cur][tc * IDIM];
#pragma unroll
            for (int i = 0; i < IDIM / 4; i++) {
                longlong2 hd = xd[i];
                a0 = dfma2(wih0[2 * i],     (ull)hd.x, a0);
                a1 = dfma2(wih0[2 * i + 1], (ull)hd.y, a1);
            }
        }
        g0s[g] = bias0 + lo2(a0) + hi2(a0) + lo2(a1) + hi2(a1);
        g1s[g] = bias1 + lo2(q0) + hi2(q0) + lo2(q1) + hi2(q1)
                       + lo2(q2) + hi2(q2) + lo2(q3) + hi2(q3);
        __syncthreads();

        // ---------- phase B: elementwise (layer0 by threads 0..63, layer1 by 64..127) ----------
        if (g < HH) {
            const float i_ = sigf(g0s[g]);
            const float f_ = sigf(g0s[HH + g]);
            const float gg = tanh_f(g0s[2 * HH + g]);
            const float o_ = sigf(g0s[3 * HH + g]);
            c0 = f_ * c0 + i_ * gg;
            h0s[g] = o_ * tanh_f(c0);
        } else if (g < 2 * HH) {
            if (t > 0) {
                const int j = g - HH;
                const float i_ = sigf(g1s[j]);
                const float f_ = sigf(g1s[HH + j]);
                const float gg = tanh_f(g1s[2 * HH + j]);
                const float o_ = sigf(g1s[3 * HH + j]);
                c1 = f_ * c1 + i_ * gg;
                h1s[j] = o_ * tanh_f(c1);
            }
        }
        __syncthreads();
    }

    // ---------- epilogue: layer1 step T-1 ----------
    {
        ull q0 = 0, q1 = 0, q2 = 0, q3 = 0;
        const longlong2* h0d = (const longlong2*)h0s;
        const longlong2* h1d = (const longlong2*)h1s;
#pragma unroll
        for (int i = 0; i < HH / 4; i++) {
            longlong2 hd = h0d[i];
            q0 = dfma2(wih1[2 * i],     (ull)hd.x, q0);
            q1 = dfma2(wih1[2 * i + 1], (ull)hd.y, q1);
            longlong2 he = h1d[i];
            q2 = dfma2(whh1[2 * i],     (ull)he.x, q2);
            q3 = dfma2(whh1[2 * i + 1], (ull)he.y, q3);
        }
        g1s[g] = bias1 + lo2(q0) + hi2(q0) + lo2(q1) + hi2(q1)
                       + lo2(q2) + hi2(q2) + lo2(q3) + hi2(q3);
        __syncthreads();
        if (g >= HH && g < 2 * HH) {
            const int j = g - HH;
            const float i_ = sigf(g1s[j]);
            const float f_ = sigf(g1s[HH + j]);
            const float gg = tanh_f(g1s[2 * HH + j]);
            const float o_ = sigf(g1s[3 * HH + j]);
            c1 = f_ * c1 + i_ * gg;
            h1s[j] = o_ * tanh_f(c1);
        }
        __syncthreads();
    }

    // ---------- FC head: warp 0 reduces 64-dim dot ----------
    if (g < 32) {
        float part = fcw[g] * h1s[g] + fcw[g + 32] * h1s[g + 32];
#pragma unroll
        for (int off = 16; off; off >>= 1)
            part += __shfl_xor_sync(0xffffffffu, part, off);
        if (g == 0) out[b] = sigf(part + fcb[0]);
    }
}

extern "C" void kernel_launch(void* const* d_in, const int* in_sizes, int n_in,
                              void* d_out, int out_size) {
    const float* x    = (const float*)d_in[0];
    const float* Wih0 = (const float*)d_in[1];
    const float* Whh0 = (const float*)d_in[2];
    const float* bih0 = (const float*)d_in[3];
    const float* bhh0 = (const float*)d_in[4];
    const float* Wih1 = (const float*)d_in[5];
    const float* Whh1 = (const float*)d_in[6];
    const float* bih1 = (const float*)d_in[7];
    const float* bhh1 = (const float*)d_in[8];
    const float* fcw  = (const float*)d_in[9];
    const float* fcb  = (const float*)d_in[10];
    float* out = (float*)d_out;

    lstm2_kernel<<<BB, NTHREADS>>>(x, Wih0, Whh0, bih0, bhh0,
                                   Wih1, Whh1, bih1, bhh1, fcw, fcb, out);
}